// round 1
// baseline (speedup 1.0000x reference)
#include <cuda_runtime.h>
#include <cstdint>

#define NTH 1024
#define KTOP 500
#define CAND_MAX 4096
#define NBIN 4096
#define NTASK 336

struct Smem {
    unsigned int hist[NBIN];                  // 16 KB
    unsigned int scan[NTH];                   // 4 KB
    unsigned long long cand[CAND_MAX];        // 32 KB
    float bx[KTOP][4];                        // 8 KB
    float sc[KTOP];                           // 2 KB
    float area[KTOP];                         // 2 KB
    unsigned long long sup[KTOP][8];          // 32 KB
    unsigned long long keepw[8];
    int T, cntAbove, cnt;
};

// order-preserving map float -> uint (ascending)
__device__ __forceinline__ unsigned int mapf(float v) {
    unsigned int u = __float_as_uint(v);
    return (u & 0x80000000u) ? ~u : (u | 0x80000000u);
}
__device__ __forceinline__ float unmapf(unsigned int u) {
    return __uint_as_float((u & 0x80000000u) ? (u ^ 0x80000000u) : ~u);
}

// find threshold bin: smallest T such that count(bin >= T) >= need.
// Writes S.T (bin) and S.cntAbove (count of bins strictly > T). All threads call.
__device__ void find_thr(Smem& S, int need, int tid, int& T_out, int& above_out) {
    int t4 = tid * 4;
    unsigned h0 = S.hist[t4], h1 = S.hist[t4 + 1], h2 = S.hist[t4 + 2], h3 = S.hist[t4 + 3];
    S.scan[tid] = h0 + h1 + h2 + h3;
    __syncthreads();
    for (int off = 1; off < NTH; off <<= 1) {
        unsigned add = (tid + off < NTH) ? S.scan[tid + off] : 0u;
        __syncthreads();
        S.scan[tid] += add;
        __syncthreads();
    }
    unsigned sfx = S.scan[tid];
    unsigned nxt = (tid < NTH - 1) ? S.scan[tid + 1] : 0u;
    if (sfx >= (unsigned)need && nxt < (unsigned)need) {
        unsigned c = nxt;
        unsigned hh[4] = { h0, h1, h2, h3 };
        for (int b = 3; b >= 0; b--) {
            if (c + hh[b] >= (unsigned)need) { S.T = t4 + b; S.cntAbove = (int)c; break; }
            c += hh[b];
        }
    }
    __syncthreads();
    T_out = S.T;
    above_out = S.cntAbove;
}

__global__ void retina_kernel(
    const float* __restrict__ cls3, const float* __restrict__ cls4, const float* __restrict__ cls5,
    const float* __restrict__ reg3, const float* __restrict__ reg4, const float* __restrict__ reg5,
    float* __restrict__ out)
{
    extern __shared__ unsigned char smem_raw[];
    Smem& S = *reinterpret_cast<Smem*>(smem_raw);
    const int tid = threadIdx.x;
    const int lane = tid & 31;

    int task = blockIdx.x;
    int lev = (task < 112) ? 0 : ((task < 224) ? 1 : 2);
    int tt  = task - lev * 112;
    int img = tt / 7;
    int cls = tt % 7;

    const int H = 192 >> lev;
    const int W = H;
    const int HW = H * W;
    const float stride = (float)(8 << lev);
    const float asize  = (float)(16 << lev);

    const float* clsP = (lev == 0) ? cls3 : ((lev == 1) ? cls4 : cls5);
    const float* regP = (lev == 0) ? reg3 : ((lev == 1) ? reg4 : reg5);

    const float* plane0 = clsP + (size_t)(img * 24 + 0 * 8 + cls + 1) * HW;
    const float* plane1 = clsP + (size_t)(img * 24 + 1 * 8 + cls + 1) * HW;
    const float* plane2 = clsP + (size_t)(img * 24 + 2 * 8 + cls + 1) * HW;
    const float* planes[3] = { plane0, plane1, plane2 };

    // ---------- init ----------
    for (int i = tid; i < NBIN; i += NTH) S.hist[i] = 0;
    if (tid == 0) S.cnt = 0;
    if (tid < 8) S.keepw[tid] = 0ull;
    __syncthreads();

    // ---------- pass 1: 12-bit histogram of mapped logit keys ----------
    for (int a = 0; a < 3; a++) {
        const float* p = planes[a];
        for (int i = tid; i < HW; i += NTH) {
            unsigned u = mapf(p[i]);
            int bin = (int)(u >> 20);
            unsigned m = __match_any_sync(0xFFFFFFFFu, bin);
            int leader = __ffs(m) - 1;
            if (lane == leader) atomicAdd(&S.hist[bin], (unsigned)__popc(m));
        }
    }
    __syncthreads();

    int T, above;
    find_thr(S, KTOP, tid, T, above);

    // ---------- pass 2: compact candidates with bin >= T ----------
    for (int a = 0; a < 3; a++) {
        const float* p = planes[a];
        for (int i = tid; i < HW; i += NTH) {
            unsigned u = mapf(p[i]);
            if ((int)(u >> 20) >= T) {
                int pos = atomicAdd(&S.cnt, 1);
                if (pos < CAND_MAX) {
                    unsigned n = (unsigned)(i * 3 + a);
                    S.cand[pos] = ((unsigned long long)u << 32) | (unsigned long long)(~n);
                }
            }
        }
    }
    __syncthreads();
    int cnt = S.cnt;

    // ---------- rare refinement: boundary bin too dense ----------
    if (cnt > CAND_MAX) {
        for (int i = tid; i < NBIN; i += NTH) S.hist[i] = 0;
        __syncthreads();
        for (int a = 0; a < 3; a++) {
            const float* p = planes[a];
            for (int i = tid; i < HW; i += NTH) {
                unsigned u = mapf(p[i]);
                bool pred = ((int)(u >> 20) == T);
                unsigned act = __ballot_sync(0xFFFFFFFFu, pred);
                if (pred) {
                    int sub = (int)((u >> 8) & 0xFFFu);
                    unsigned m = __match_any_sync(act, sub);
                    int leader = __ffs(m) - 1;
                    if (lane == leader) atomicAdd(&S.hist[sub], (unsigned)__popc(m));
                }
            }
        }
        __syncthreads();
        int T2, ab2;
        find_thr(S, KTOP - above, tid, T2, ab2);
        if (tid == 0) S.cnt = 0;
        __syncthreads();
        for (int a = 0; a < 3; a++) {
            const float* p = planes[a];
            for (int i = tid; i < HW; i += NTH) {
                unsigned u = mapf(p[i]);
                int bin = (int)(u >> 20);
                if (bin > T || (bin == T && (int)((u >> 8) & 0xFFFu) >= T2)) {
                    int pos = atomicAdd(&S.cnt, 1);
                    if (pos < CAND_MAX) {
                        unsigned n = (unsigned)(i * 3 + a);
                        S.cand[pos] = ((unsigned long long)u << 32) | (unsigned long long)(~n);
                    }
                }
            }
        }
        __syncthreads();
        cnt = S.cnt;
    }
    if (cnt > CAND_MAX) cnt = CAND_MAX;

    // ---------- bitonic sort (descending) of cnt candidates padded to M ----------
    int M = 512;
    while (M < cnt) M <<= 1;
    for (int i = cnt + tid; i < M; i += NTH) S.cand[i] = 0ull;
    __syncthreads();
    for (int k = 2; k <= M; k <<= 1) {
        for (int j = k >> 1; j > 0; j >>= 1) {
            for (int i = tid; i < M; i += NTH) {
                int ixj = i ^ j;
                if (ixj > i) {
                    unsigned long long a = S.cand[i], b = S.cand[ixj];
                    bool sw = ((i & k) == 0) ? (a < b) : (a > b);
                    if (sw) { S.cand[i] = b; S.cand[ixj] = a; }
                }
            }
            __syncthreads();
        }
    }

    // ---------- extract top-500, decode boxes, write boxes/scores/labels ----------
    long long tbase = (long long)((lev * 16 + img) * 7 + cls) * KTOP;
    float* obox  = out + tbase * 4;
    float* osc   = out + 672000 + tbase;
    float* okeep = out + 840000 + tbase;
    float* olab  = out + 1008000 + tbase;

    for (int r = tid; r < KTOP; r += NTH) {
        unsigned long long key = S.cand[r];
        unsigned u = (unsigned)(key >> 32);
        unsigned n = ~((unsigned)key);
        float logit = unmapf(u);
        float score = 1.0f / (1.0f + expf(-logit));

        int a = (int)(n % 3u);
        int p = (int)(n / 3u);
        int x = p % W;
        int y = p / W;
        float sqv = (a == 0) ? 0.70710678118654752f : ((a == 1) ? 1.0f : 1.41421356237309505f);
        float cx0 = ((float)x + 0.5f) * stride;
        float cy0 = ((float)y + 0.5f) * stride;
        float wa0 = asize * sqv;
        float ha0 = asize / sqv;
        float ax1 = cx0 - 0.5f * wa0, ay1 = cy0 - 0.5f * ha0;
        float ax2 = cx0 + 0.5f * wa0, ay2 = cy0 + 0.5f * ha0;
        float wa = ax2 - ax1, ha = ay2 - ay1;
        float cxa = ax1 + 0.5f * wa, cya = ay1 + 0.5f * ha;

        size_t rb = (size_t)(img * 12 + a * 4) * HW + (size_t)p;
        float dx = regP[rb];
        float dy = regP[rb + HW];
        float dw = regP[rb + 2 * (size_t)HW];
        float dh = regP[rb + 3 * (size_t)HW];

        float cx = dx * wa + cxa;
        float cy = dy * ha + cya;
        float bw = expf(dw) * wa;
        float bh = expf(dh) * ha;
        float bx1 = cx - 0.5f * bw, by1 = cy - 0.5f * bh;
        float bx2 = cx + 0.5f * bw, by2 = cy + 0.5f * bh;

        S.bx[r][0] = bx1; S.bx[r][1] = by1; S.bx[r][2] = bx2; S.bx[r][3] = by2;
        S.sc[r] = score;
        S.area[r] = (bx2 - bx1) * (by2 - by1);

        obox[r * 4 + 0] = bx1; obox[r * 4 + 1] = by1;
        obox[r * 4 + 2] = bx2; obox[r * 4 + 3] = by2;
        osc[r] = score;
        olab[r] = (float)cls;
        if (score > 0.05f) atomicOr(&S.keepw[r >> 6], 1ull << (r & 63));
    }
    __syncthreads();

    // ---------- suppression bitmask matrix ----------
    for (int it = tid; it < KTOP * 8; it += NTH) {
        int i = it >> 3;
        int w = it & 7;
        float ix1 = S.bx[i][0], iy1 = S.bx[i][1], ix2 = S.bx[i][2], iy2 = S.bx[i][3];
        float ai = S.area[i];
        unsigned long long bits = 0ull;
        int jbase = w << 6;
        int jend = KTOP - jbase; if (jend > 64) jend = 64;
        for (int b = 0; b < jend; b++) {
            int j = jbase + b;
            float xx1 = fmaxf(ix1, S.bx[j][0]);
            float yy1 = fmaxf(iy1, S.bx[j][1]);
            float xx2 = fminf(ix2, S.bx[j][2]);
            float yy2 = fminf(iy2, S.bx[j][3]);
            float inter = fmaxf(xx2 - xx1, 0.0f) * fmaxf(yy2 - yy1, 0.0f);
            float uni = fmaxf(ai + S.area[j] - inter, 1e-9f);
            if (inter > 0.5f * uni) bits |= (1ull << b);
        }
        S.sup[i][w] = bits;
    }
    __syncthreads();

    // ---------- greedy NMS (single thread, skips dead rows via ffs) ----------
    if (tid == 0) {
        unsigned long long kw[8];
        #pragma unroll
        for (int w = 0; w < 8; w++) kw[w] = S.keepw[w];
        #pragma unroll
        for (int w = 0; w < 8; w++) {
            unsigned long long above = ~0ull;
            while (true) {
                unsigned long long rem = kw[w] & above;
                if (!rem) break;
                int b = __ffsll((long long)rem) - 1;
                int i = (w << 6) + b;
                above = (b == 63) ? 0ull : ~((2ull << b) - 1ull);
                kw[w] &= ~(S.sup[i][w] & above);
                #pragma unroll
                for (int w2 = w + 1; w2 < 8; w2++) kw[w2] &= ~S.sup[i][w2];
            }
        }
        #pragma unroll
        for (int w = 0; w < 8; w++) S.keepw[w] = kw[w];
    }
    __syncthreads();

    for (int r = tid; r < KTOP; r += NTH) {
        okeep[r] = ((S.keepw[r >> 6] >> (r & 63)) & 1ull) ? 1.0f : 0.0f;
    }
}

extern "C" void kernel_launch(void* const* d_in, const int* in_sizes, int n_in,
                              void* d_out, int out_size) {
    const float *cls3 = nullptr, *cls4 = nullptr, *cls5 = nullptr;
    const float *reg3 = nullptr, *reg4 = nullptr, *reg5 = nullptr;
    for (int i = 0; i < n_in; i++) {
        switch (in_sizes[i]) {
            case 14155776: cls3 = (const float*)d_in[i]; break;
            case 7077888:  reg3 = (const float*)d_in[i]; break;
            case 3538944:  cls4 = (const float*)d_in[i]; break;
            case 1769472:  reg4 = (const float*)d_in[i]; break;
            case 884736:   cls5 = (const float*)d_in[i]; break;
            case 442368:   reg5 = (const float*)d_in[i]; break;
        }
    }
    cudaFuncSetAttribute(retina_kernel, cudaFuncAttributeMaxDynamicSharedMemorySize,
                         (int)sizeof(Smem));
    retina_kernel<<<NTASK, NTH, sizeof(Smem)>>>(cls3, cls4, cls5, reg3, reg4, reg5,
                                                (float*)d_out);
}

// round 2
// speedup vs baseline: 3.5229x; 3.5229x over previous
#include <cuda_runtime.h>
#include <cstdint>

#define NTH 1024
#define KTOP 500
#define CAND_MAX 4096
#define NBIN 4096
#define NTASK 336

struct Smem {
    union {
        struct { unsigned int hist[NBIN]; unsigned int scan[NTH]; } h;  // 20 KB (fallback only)
        unsigned long long cand[CAND_MAX];                              // 32 KB
    } u;
    float4 bx4[512];                          // 8 KB (padded boxes)
    unsigned long long sup[KTOP][8];          // 32 KB
    unsigned long long keepw[8];
    int T, cntAbove, cnt;
};

// order-preserving map float -> uint (ascending)
__device__ __forceinline__ unsigned int mapf(float v) {
    unsigned int u = __float_as_uint(v);
    return (u & 0x80000000u) ? ~u : (u | 0x80000000u);
}
__device__ __forceinline__ float unmapf(unsigned int u) {
    return __uint_as_float((u & 0x80000000u) ? (u ^ 0x80000000u) : ~u);
}

// find threshold bin: smallest T such that count(bin >= T) >= need.
__device__ void find_thr(Smem& S, int need, int tid, int& T_out, int& above_out) {
    int t4 = tid * 4;
    unsigned h0 = S.u.h.hist[t4], h1 = S.u.h.hist[t4 + 1];
    unsigned h2 = S.u.h.hist[t4 + 2], h3 = S.u.h.hist[t4 + 3];
    S.u.h.scan[tid] = h0 + h1 + h2 + h3;
    __syncthreads();
    for (int off = 1; off < NTH; off <<= 1) {
        unsigned add = (tid + off < NTH) ? S.u.h.scan[tid + off] : 0u;
        __syncthreads();
        S.u.h.scan[tid] += add;
        __syncthreads();
    }
    unsigned sfx = S.u.h.scan[tid];
    unsigned nxt = (tid < NTH - 1) ? S.u.h.scan[tid + 1] : 0u;
    if (sfx >= (unsigned)need && nxt < (unsigned)need) {
        unsigned c = nxt;
        unsigned hh[4] = { h0, h1, h2, h3 };
        for (int b = 3; b >= 0; b--) {
            if (c + hh[b] >= (unsigned)need) { S.T = t4 + b; S.cntAbove = (int)c; break; }
            c += hh[b];
        }
    }
    __syncthreads();
    T_out = S.T;
    above_out = S.cntAbove;
}

__global__ __launch_bounds__(NTH, 2) void retina_kernel(
    const float* __restrict__ cls3, const float* __restrict__ cls4, const float* __restrict__ cls5,
    const float* __restrict__ reg3, const float* __restrict__ reg4, const float* __restrict__ reg5,
    float* __restrict__ out)
{
    extern __shared__ unsigned char smem_raw[];
    Smem& S = *reinterpret_cast<Smem*>(smem_raw);
    const int tid = threadIdx.x;
    const int lane = tid & 31;

    int task = blockIdx.x;
    int lev = (task < 112) ? 0 : ((task < 224) ? 1 : 2);
    int tt  = task - lev * 112;
    int img = tt / 7;
    int cls = tt % 7;

    const int H = 192 >> lev;
    const int W = H;
    const int HW = H * W;
    const float stride = (float)(8 << lev);
    const float asize  = (float)(16 << lev);

    const float* clsP = (lev == 0) ? cls3 : ((lev == 1) ? cls4 : cls5);
    const float* regP = (lev == 0) ? reg3 : ((lev == 1) ? reg4 : reg5);

    const float* plane0 = clsP + (size_t)(img * 24 + 0 * 8 + cls + 1) * HW;
    const float* plane1 = clsP + (size_t)(img * 24 + 1 * 8 + cls + 1) * HW;
    const float* plane2 = clsP + (size_t)(img * 24 + 2 * 8 + cls + 1) * HW;
    const float* planes[3] = { plane0, plane1, plane2 };

    // ---------- init ----------
    if (tid == 0) S.cnt = 0;
    if (tid < 8) S.keepw[tid] = 0ull;
    __syncthreads();

    // ---------- fast path: single pass threshold compaction ----------
    // thresholds are ~10 sigma below the expected 500th-largest logit per level;
    // the exact histogram fallback below guarantees correctness for any input.
    float thf = (lev == 0) ? -1.55f : ((lev == 1) ? -2.10f : -2.80f);
    unsigned thU = mapf(thf);

    for (int a = 0; a < 3; a++) {
        const float4* p4 = (const float4*)planes[a];
        int nv4 = HW >> 2;
        for (int i4 = tid; i4 < nv4; i4 += NTH) {
            float4 v = p4[i4];
            #pragma unroll
            for (int e = 0; e < 4; e++) {
                float f = (e == 0) ? v.x : (e == 1) ? v.y : (e == 2) ? v.z : v.w;
                unsigned m = mapf(f);
                if (m > thU) {
                    int pos = atomicAdd(&S.cnt, 1);
                    if (pos < CAND_MAX) {
                        unsigned n = (unsigned)((i4 * 4 + e) * 3 + a);
                        S.u.cand[pos] = ((unsigned long long)m << 32) | (unsigned long long)(~n);
                    }
                }
            }
        }
    }
    __syncthreads();
    int cnt = S.cnt;

    // ---------- exact fallback: 12-bit histogram select (rare) ----------
    if (cnt < KTOP || cnt > CAND_MAX) {
        for (int i = tid; i < NBIN; i += NTH) S.u.h.hist[i] = 0;
        __syncthreads();
        for (int a = 0; a < 3; a++) {
            const float* p = planes[a];
            for (int i = tid; i < HW; i += NTH) {
                unsigned u = mapf(p[i]);
                int bin = (int)(u >> 20);
                unsigned m = __match_any_sync(__activemask(), bin);
                int leader = __ffs(m) - 1;
                if (lane == leader) atomicAdd(&S.u.h.hist[bin], (unsigned)__popc(m));
            }
        }
        __syncthreads();
        int T, above;
        find_thr(S, KTOP, tid, T, above);
        if (tid == 0) S.cnt = 0;
        __syncthreads();
        for (int a = 0; a < 3; a++) {
            const float* p = planes[a];
            for (int i = tid; i < HW; i += NTH) {
                unsigned u = mapf(p[i]);
                if ((int)(u >> 20) >= T) {
                    int pos = atomicAdd(&S.cnt, 1);
                    if (pos < CAND_MAX) {
                        unsigned n = (unsigned)(i * 3 + a);
                        S.u.cand[pos] = ((unsigned long long)u << 32) | (unsigned long long)(~n);
                    }
                }
            }
        }
        __syncthreads();
        cnt = S.cnt;

        if (cnt > CAND_MAX) {
            // refine on bits [19:8] within boundary bin T
            for (int i = tid; i < NBIN; i += NTH) S.u.h.hist[i] = 0;
            __syncthreads();
            for (int a = 0; a < 3; a++) {
                const float* p = planes[a];
                for (int i = tid; i < HW; i += NTH) {
                    unsigned u = mapf(p[i]);
                    if ((int)(u >> 20) == T)
                        atomicAdd(&S.u.h.hist[(u >> 8) & 0xFFFu], 1u);
                }
            }
            __syncthreads();
            int T2, ab2;
            find_thr(S, KTOP - above, tid, T2, ab2);
            if (tid == 0) S.cnt = 0;
            __syncthreads();
            for (int a = 0; a < 3; a++) {
                const float* p = planes[a];
                for (int i = tid; i < HW; i += NTH) {
                    unsigned u = mapf(p[i]);
                    int bin = (int)(u >> 20);
                    if (bin > T || (bin == T && (int)((u >> 8) & 0xFFFu) >= T2)) {
                        int pos = atomicAdd(&S.cnt, 1);
                        if (pos < CAND_MAX) {
                            unsigned n = (unsigned)(i * 3 + a);
                            S.u.cand[pos] = ((unsigned long long)u << 32) | (unsigned long long)(~n);
                        }
                    }
                }
            }
            __syncthreads();
            cnt = S.cnt;
        }
    }
    if (cnt > CAND_MAX) cnt = CAND_MAX;

    // ---------- bitonic sort (descending), pad to M ----------
    int M = 512;
    while (M < cnt) M <<= 1;
    for (int i = cnt + tid; i < M; i += NTH) S.u.cand[i] = 0ull;
    __syncthreads();
    for (int k = 2; k <= M; k <<= 1) {
        for (int j = k >> 1; j > 0; j >>= 1) {
            if (j >= 16) __syncthreads(); else __syncwarp();
            for (int i = tid; i < M; i += NTH) {
                int ixj = i ^ j;
                if (ixj > i) {
                    unsigned long long a = S.u.cand[i], b = S.u.cand[ixj];
                    bool sw = ((i & k) == 0) ? (a < b) : (a > b);
                    if (sw) { S.u.cand[i] = b; S.u.cand[ixj] = a; }
                }
            }
        }
    }
    __syncthreads();

    // ---------- decode top-500, write boxes/scores/labels ----------
    long long tbase = (long long)((lev * 16 + img) * 7 + cls) * KTOP;
    float* obox  = out + tbase * 4;
    float* osc   = out + 672000 + tbase;
    float* okeep = out + 840000 + tbase;
    float* olab  = out + 1008000 + tbase;

    if (tid < 512) {
        int r = tid;
        bool valid_bit = false;
        if (r < KTOP) {
            unsigned long long key = S.u.cand[r];
            unsigned u = (unsigned)(key >> 32);
            unsigned n = ~((unsigned)key);
            float logit = unmapf(u);
            float score = 1.0f / (1.0f + expf(-logit));

            int a = (int)(n % 3u);
            int p = (int)(n / 3u);
            int x = p % W;
            int y = p / W;
            float sqv = (a == 0) ? 0.70710678118654752f : ((a == 1) ? 1.0f : 1.41421356237309505f);
            float wa = asize * sqv;
            float ha = asize / sqv;
            float cxa = ((float)x + 0.5f) * stride;
            float cya = ((float)y + 0.5f) * stride;

            size_t rb = (size_t)(img * 12 + a * 4) * HW + (size_t)p;
            float dx = regP[rb];
            float dy = regP[rb + HW];
            float dw = regP[rb + 2 * (size_t)HW];
            float dh = regP[rb + 3 * (size_t)HW];

            float cx = dx * wa + cxa;
            float cy = dy * ha + cya;
            float bw = expf(dw) * wa;
            float bh = expf(dh) * ha;
            float bx1 = cx - 0.5f * bw, by1 = cy - 0.5f * bh;
            float bx2 = cx + 0.5f * bw, by2 = cy + 0.5f * bh;

            S.bx4[r] = make_float4(bx1, by1, bx2, by2);
            obox[r * 4 + 0] = bx1; obox[r * 4 + 1] = by1;
            obox[r * 4 + 2] = bx2; obox[r * 4 + 3] = by2;
            osc[r] = score;
            olab[r] = (float)cls;
            valid_bit = (score > 0.05f);
        } else {
            S.bx4[r] = make_float4(1e30f, 1e30f, 1e30f, 1e30f);
        }
        unsigned b = __ballot_sync(0xFFFFFFFFu, valid_bit);
        if (lane == 0 && b)
            atomicOr(&S.keepw[r >> 6], (unsigned long long)b << ((r >> 5 & 1) * 32));
    }
    __syncthreads();

    // ---------- suppression bitmask matrix: warp-tiled 32x64, j-broadcast ----------
    {
        int warpId = tid >> 5;
        for (int t = warpId; t < 128; t += 32) {
            int tr = t >> 3, w = t & 7;
            int r0 = tr << 5;
            if (w * 64 + 63 <= r0) continue;      // tile entirely j<=i: never used
            int i = r0 + lane;
            float4 bi = S.bx4[i];
            float ai = (bi.z - bi.x) * (bi.w - bi.y);
            unsigned long long bits = 0ull;
            int jb = w << 6;
            #pragma unroll 4
            for (int b = 0; b < 64; b++) {
                float4 bj = S.bx4[jb + b];        // broadcast load
                float xx1 = fmaxf(bi.x, bj.x);
                float yy1 = fmaxf(bi.y, bj.y);
                float xx2 = fminf(bi.z, bj.z);
                float yy2 = fminf(bi.w, bj.w);
                float inter = fmaxf(xx2 - xx1, 0.0f) * fmaxf(yy2 - yy1, 0.0f);
                float aj = (bj.z - bj.x) * (bj.w - bj.y);
                float uni = fmaxf(ai + aj - inter, 1e-9f);
                if (inter > 0.5f * uni) bits |= (1ull << b);
            }
            if (i < KTOP) S.sup[i][w] = bits;
        }
    }
    __syncthreads();

    // ---------- greedy NMS (single thread, ffs-skips dead rows) ----------
    if (tid == 0) {
        unsigned long long kw[8];
        #pragma unroll
        for (int w = 0; w < 8; w++) kw[w] = S.keepw[w];
        #pragma unroll
        for (int w = 0; w < 8; w++) {
            unsigned long long above = ~0ull;
            while (true) {
                unsigned long long rem = kw[w] & above;
                if (!rem) break;
                int b = __ffsll((long long)rem) - 1;
                int i = (w << 6) + b;
                above = (b == 63) ? 0ull : ~((2ull << b) - 1ull);
                kw[w] &= ~(S.sup[i][w] & above);
                #pragma unroll
                for (int w2 = w + 1; w2 < 8; w2++) kw[w2] &= ~S.sup[i][w2];
            }
        }
        #pragma unroll
        for (int w = 0; w < 8; w++) S.keepw[w] = kw[w];
    }
    __syncthreads();

    for (int r = tid; r < KTOP; r += NTH)
        okeep[r] = ((S.keepw[r >> 6] >> (r & 63)) & 1ull) ? 1.0f : 0.0f;
}

extern "C" void kernel_launch(void* const* d_in, const int* in_sizes, int n_in,
                              void* d_out, int out_size) {
    const float *cls3 = nullptr, *cls4 = nullptr, *cls5 = nullptr;
    const float *reg3 = nullptr, *reg4 = nullptr, *reg5 = nullptr;
    for (int i = 0; i < n_in; i++) {
        switch (in_sizes[i]) {
            case 14155776: cls3 = (const float*)d_in[i]; break;
            case 7077888:  reg3 = (const float*)d_in[i]; break;
            case 3538944:  cls4 = (const float*)d_in[i]; break;
            case 1769472:  reg4 = (const float*)d_in[i]; break;
            case 884736:   cls5 = (const float*)d_in[i]; break;
            case 442368:   reg5 = (const float*)d_in[i]; break;
        }
    }
    cudaFuncSetAttribute(retina_kernel, cudaFuncAttributeMaxDynamicSharedMemorySize,
                         (int)sizeof(Smem));
    retina_kernel<<<NTASK, NTH, sizeof(Smem)>>>(cls3, cls4, cls5, reg3, reg4, reg5,
                                                (float*)d_out);
}